// round 6
// baseline (speedup 1.0000x reference)
#include <cuda_runtime.h>

typedef unsigned long long ull;

#define BATCH 131072
#define MTILE 64
#define NBLK  (BATCH / MTILE)
#define OUTY  ((size_t)BATCH * 64)

// h2 scratch between the two kernels (static __device__ allocation is the
// sanctioned scratch mechanism; no runtime alloc).
__device__ float g_h2[(size_t)BATCH * 512];

// ---------- f32x2 helpers ----------
__device__ __forceinline__ ull pk2(float a, float b) {
    ull r; asm("mov.b64 %0,{%1,%2};" : "=l"(r) : "f"(a), "f"(b)); return r;
}
__device__ __forceinline__ void up2(ull v, float &a, float &b) {
    asm("mov.b64 {%0,%1},%2;" : "=f"(a), "=f"(b) : "l"(v));
}
__device__ __forceinline__ void fma2(ull &d, ull a, ull b) {
    asm("fma.rn.f32x2 %0,%1,%2,%0;" : "+l"(d) : "l"(a), "l"(b));
}
struct __align__(16) U2 { ull a, b; };

// ---------- GEMM: C[64 x 256] += A[64 x K] @ W[K x 512][:, n0:n0+256] ----------
// acc[4][8] : rows r0..r0+3, cols n0+tc*16 .. +15 as f32x2 pairs.
// A in smem (row-major, stride lda). W staged gmem->smem [16][256] tiles,
// register-prefetch double buffering.
template <int K>
__device__ __forceinline__ void mm256(ull acc[4][8], const float* sA, int lda,
                                      const float* gW, int n0, float* wst,
                                      int tid, int r0, int tc) {
    const int kr = tid >> 4;
    const int cc = (tid & 15) << 4;
    const float* gsrc = gW + (size_t)kr * 512 + n0 + cc;
    float4 pf[4];
#pragma unroll
    for (int q = 0; q < 4; q++) pf[q] = *(const float4*)(gsrc + 4 * q);

#pragma unroll 1
    for (int t = 0; t < K / 16; t++) {
        __syncthreads();                       // prior consumers of wst done
        float4* wd = (float4*)(wst + kr * 256 + cc);
#pragma unroll
        for (int q = 0; q < 4; q++) wd[q] = pf[q];
        __syncthreads();                       // wst tile ready
        if (t + 1 < K / 16) {
            const float* gs = gsrc + (size_t)(t + 1) * 16 * 512;
#pragma unroll
            for (int q = 0; q < 4; q++) pf[q] = *(const float4*)(gs + 4 * q);
        }
#pragma unroll
        for (int kk = 0; kk < 16; kk++) {
            const int k = t * 16 + kk;
            float a0 = sA[(r0 + 0) * lda + k];
            float a1 = sA[(r0 + 1) * lda + k];
            float a2 = sA[(r0 + 2) * lda + k];
            float a3 = sA[(r0 + 3) * lda + k];
            ull aa[4] = { pk2(a0, a0), pk2(a1, a1), pk2(a2, a2), pk2(a3, a3) };
            const U2* bp = (const U2*)(wst + kk * 256 + tc * 16);
            U2 b0 = bp[0], b1 = bp[1], b2 = bp[2], b3 = bp[3];
            ull bs[8] = { b0.a, b0.b, b1.a, b1.b, b2.a, b2.b, b3.a, b3.b };
#pragma unroll
            for (int r = 0; r < 4; r++)
#pragma unroll
                for (int j = 0; j < 8; j++) fma2(acc[r][j], aa[r], bs[j]);
        }
    }
}

// ---------- Layer-3 GEMM: 192 padded cols (8 spline groups x 24) ----------
// Real W3 cols (8c+g)*23+jj for jj<23; padded col 23 of each group is zero.
__device__ __forceinline__ void mm192(ull acc[4][6], const float* sA,
                                      const float* W3, int chunk, float* wst,
                                      int tid, int r0, int tc) {
    int  goff[12]; bool gv[12];
#pragma unroll
    for (int i = 0; i < 12; i++) {
        int idx = tid + (i << 8);              // 0..3071 over [16][192]
        int kr = idx / 192, p = idx - kr * 192;
        int g = p / 24, jj = p - g * 24;
        gv[i]   = (jj < 23);
        goff[i] = kr * 736 + (chunk * 8 + g) * 23 + jj;
    }
    float pf[12];
#pragma unroll
    for (int i = 0; i < 12; i++) pf[i] = gv[i] ? W3[(size_t)goff[i]] : 0.f;

#pragma unroll 1
    for (int t = 0; t < 32; t++) {
        __syncthreads();
#pragma unroll
        for (int i = 0; i < 12; i++) wst[tid + (i << 8)] = pf[i];
        __syncthreads();
        if (t + 1 < 32) {
            const float* gs = W3 + (size_t)(t + 1) * 16 * 736;
#pragma unroll
            for (int i = 0; i < 12; i++) pf[i] = gv[i] ? gs[goff[i]] : 0.f;
        }
#pragma unroll
        for (int kk = 0; kk < 16; kk++) {
            const int k = t * 16 + kk;
            float a0 = sA[(r0 + 0) * 512 + k];
            float a1 = sA[(r0 + 1) * 512 + k];
            float a2 = sA[(r0 + 2) * 512 + k];
            float a3 = sA[(r0 + 3) * 512 + k];
            ull aa[4] = { pk2(a0, a0), pk2(a1, a1), pk2(a2, a2), pk2(a3, a3) };
            const U2* bp = (const U2*)(wst + kk * 192 + tc * 12);
            U2 b0 = bp[0], b1 = bp[1], b2 = bp[2];
            ull bs[6] = { b0.a, b0.b, b1.a, b1.b, b2.a, b2.b };
#pragma unroll
            for (int r = 0; r < 4; r++)
#pragma unroll
                for (int j = 0; j < 6; j++) fma2(acc[r][j], aa[r], bs[j]);
        }
    }
}

// ---------- kernel A: layers 1+2 -> g_h2 ----------
// smem: hs[64][512]=32768f | wst[16][256]=4096f | xms[64][32]=2048f  (152 KB)
__global__ void __launch_bounds__(256, 1)
kA(const float* __restrict__ x,
   const float* __restrict__ W1, const float* __restrict__ b1,
   const float* __restrict__ W2, const float* __restrict__ b2) {
    extern __shared__ float sm[];
    float* hs  = sm;
    float* wst = sm + 32768;
    float* xms = sm + 36864;
    const int tid = threadIdx.x;
    const int m0  = blockIdx.x * MTILE;
    const int r0  = (tid >> 4) << 2;
    const int tc  = tid & 15;

    // load x_masked (cols 0..31) into smem
    for (int i = tid; i < 512; i += 256) {
        int row = i >> 3, q = i & 7;
        float4 v = *(const float4*)(x + (size_t)(m0 + row) * 64 + 4 * q);
        *(float4*)(xms + row * 32 + 4 * q) = v;
    }
    // (mm256's leading __syncthreads orders xms writes before reads)

    // ---- layer 1: h1 = relu(xm @ W1 + b1) -> hs ----
#pragma unroll 1
    for (int p = 0; p < 2; p++) {
        const int n0 = p * 256;
        ull acc[4][8];
#pragma unroll
        for (int j = 0; j < 8; j++) {
            float2 bb = *(const float2*)(b1 + n0 + tc * 16 + 2 * j);
            ull bi = pk2(bb.x, bb.y);
#pragma unroll
            for (int r = 0; r < 4; r++) acc[r][j] = bi;
        }
        mm256<32>(acc, xms, 32, W1, n0, wst, tid, r0, tc);
#pragma unroll
        for (int r = 0; r < 4; r++)
#pragma unroll
            for (int j = 0; j < 8; j++) {
                float v0, v1; up2(acc[r][j], v0, v1);
                *(ull*)(hs + (r0 + r) * 512 + n0 + tc * 16 + 2 * j) =
                    pk2(fmaxf(v0, 0.f), fmaxf(v1, 0.f));
            }
    }

    // ---- layer 2: h2 = relu(h1 @ W2 + b2) -> gmem scratch ----
#pragma unroll 1
    for (int p = 0; p < 2; p++) {
        const int n0 = p * 256;
        ull acc[4][8];
#pragma unroll
        for (int j = 0; j < 8; j++) {
            float2 bb = *(const float2*)(b2 + n0 + tc * 16 + 2 * j);
            ull bi = pk2(bb.x, bb.y);
#pragma unroll
            for (int r = 0; r < 4; r++) acc[r][j] = bi;
        }
        mm256<512>(acc, hs, 512, W2, n0, wst, tid, r0, tc);
#pragma unroll
        for (int r = 0; r < 4; r++) {
            float4 o[4];
#pragma unroll
            for (int j = 0; j < 8; j++) {
                float v0, v1; up2(acc[r][j], v0, v1);
                ((float*)o)[2 * j]     = fmaxf(v0, 0.f);
                ((float*)o)[2 * j + 1] = fmaxf(v1, 0.f);
            }
            float4* dst = (float4*)(g_h2 + (size_t)(m0 + r0 + r) * 512 + n0 + tc * 16);
#pragma unroll
            for (int q = 0; q < 4; q++) dst[q] = o[q];
        }
    }
}

// ---------- kernel B: layer 3 + RQ spline + outputs ----------
// smem: hs 32768f | wst 3072f | raw 12288f | xt 2048f | ldp 2112f = 52288f (204 KB)
__global__ void __launch_bounds__(256, 1)
kB(const float* __restrict__ x, const float* __restrict__ W3,
   const float* __restrict__ b3, float* __restrict__ out) {
    extern __shared__ float sm[];
    float* hs  = sm;
    float* wst = sm + 32768;
    float* raw = sm + 35840;
    float* xt  = sm + 48128;
    float* ldp = sm + 50176;   // [64][33] padded, conflict-free
    const int tid = threadIdx.x;
    const int m0  = blockIdx.x * MTILE;
    const int r0  = (tid >> 4) << 2;
    const int tc  = tid & 15;

    // load h2 tile (fully coalesced float4)
    const float4* hsrc = (const float4*)(g_h2 + (size_t)m0 * 512);
    float4* hd4 = (float4*)hs;
#pragma unroll 8
    for (int i = 0; i < 32; i++) hd4[tid + 256 * i] = hsrc[tid + 256 * i];

    // x tile: cols 0..31 passthrough -> out, cols 32..63 -> xt
    for (int i = tid; i < 1024; i += 256) {
        int row = i >> 4, q = i & 15;
        float4 v = *(const float4*)(x + (size_t)(m0 + row) * 64 + 4 * q);
        if (q < 8) *(float4*)(out + (size_t)(m0 + row) * 64 + 4 * q) = v;
        else       *(float4*)(xt + row * 32 + 4 * (q - 8)) = v;
    }

#pragma unroll 1
    for (int c = 0; c < 4; c++) {
        // bias init (padded col of each 24-group = 0)
        ull acc[4][6];
#pragma unroll
        for (int j = 0; j < 6; j++) {
            int p = tc * 12 + 2 * j;
            int g0 = p / 24,       j0 = p - g0 * 24;
            int g1 = (p + 1) / 24, j1 = (p + 1) - g1 * 24;
            float v0 = (j0 < 23) ? b3[(c * 8 + g0) * 23 + j0] : 0.f;
            float v1 = (j1 < 23) ? b3[(c * 8 + g1) * 23 + j1] : 0.f;
            ull bi = pk2(v0, v1);
#pragma unroll
            for (int r = 0; r < 4; r++) acc[r][j] = bi;
        }
        mm192(acc, hs, W3, c, wst, tid, r0, tc);

        // raw tile -> smem for the per-dim reshuffle
#pragma unroll
        for (int r = 0; r < 4; r++)
#pragma unroll
            for (int j = 0; j < 6; j++)
                *(ull*)(raw + (r0 + r) * 192 + tc * 12 + 2 * j) = acc[r][j];
        __syncthreads();

        // spline epilogue: 512 (row,dim) tasks, 2 per thread
#pragma unroll 1
        for (int i = 0; i < 2; i++) {
            int task = tid + 256 * i;
            int row = task >> 3, g = task & 7;
            const float* rb = raw + row * 192 + g * 24;
            float xv = xt[row * 32 + c * 8 + g];

            float wr[8], hr[8];
#pragma unroll
            for (int q = 0; q < 8; q++) { wr[q] = rb[q]; hr[q] = rb[8 + q]; }
            float mw = wr[0], mh = hr[0];
#pragma unroll
            for (int q = 1; q < 8; q++) { mw = fmaxf(mw, wr[q]); mh = fmaxf(mh, hr[q]); }
            float sw = 0.f, sh = 0.f;
#pragma unroll
            for (int q = 0; q < 8; q++) {
                wr[q] = expf(wr[q] - mw); sw += wr[q];
                hr[q] = expf(hr[q] - mh); sh += hr[q];
            }
            float fw = 6.f / sw, fh = 6.f / sh;
#pragma unroll
            for (int q = 0; q < 8; q++) { wr[q] *= fw; hr[q] *= fh; }

            float dv[9]; dv[0] = 1.f; dv[8] = 1.f;
#pragma unroll
            for (int q = 0; q < 7; q++) {
                float v = rb[16 + q];
                dv[q + 1] = fmaxf(v, 0.f) + log1pf(expf(-fabsf(v)));   // softplus
            }
            float cw[9], ch[9]; cw[0] = -3.f; ch[0] = -3.f;
#pragma unroll
            for (int q = 0; q < 8; q++) { cw[q + 1] = cw[q] + wr[q]; ch[q + 1] = ch[q] + hr[q]; }

            float xc = fminf(fmaxf(xv, -3.f + 1e-6f), 3.f - 1e-6f);
            int bin = 0;
#pragma unroll
            for (int q = 1; q < 9; q++) bin += (cw[q] < xc) ? 1 : 0;
            bin = min(bin, 7);

            // register gathers via unrolled selects (no local-mem spill)
            float wk = wr[0], hk = hr[0], dk = dv[0], dk1 = dv[1];
            float cwk = cw[0], chk = ch[0];
#pragma unroll
            for (int q = 1; q < 8; q++) {
                bool s = (bin >= q);
                wk  = s ? wr[q] : wk;   hk  = s ? hr[q] : hk;
                dk  = s ? dv[q] : dk;   dk1 = s ? dv[q + 1] : dk1;
                cwk = s ? cw[q] : cwk;  chk = s ? ch[q] : chk;
            }
            float xi = fminf(fmaxf((xc - cwk) / wk, 1e-6f), 1.f - 1e-6f);
            float s  = hk / wk;
            float om = 1.f - xi;
            float num = hk * (s * xi * xi + dk * xi * om);
            float den = s + (dk + dk1 - 2.f * s) * xi * om;
            float yin = chk + num / den;
            float t1  = s * s * (dk1 * xi * xi + 2.f * s * xi * om + dk * om * om);
            float ldin = logf(t1 + 1e-8f) - logf(den * den + 1e-8f);
            bool inside = (xv >= -3.f) && (xv <= 3.f);
            int dim = c * 8 + g;
            out[(size_t)(m0 + row) * 64 + 32 + dim] = inside ? yin : xv;
            ldp[row * 33 + dim] = inside ? ldin : 0.f;
        }
        __syncthreads();
    }

    // log_det reduction per row (deterministic, conflict-free)
    if (tid < 64) {
        float s = 0.f;
#pragma unroll
        for (int d = 0; d < 32; d++) s += ldp[tid * 33 + d];
        out[OUTY + m0 + tid] = s;
    }
}

extern "C" void kernel_launch(void* const* d_in, const int* in_sizes, int n_in,
                              void* d_out, int out_size) {
    const float* x  = (const float*)d_in[0];
    const float* W1 = (const float*)d_in[1];
    const float* b1 = (const float*)d_in[2];
    const float* W2 = (const float*)d_in[3];
    const float* b2 = (const float*)d_in[4];
    const float* W3 = (const float*)d_in[5];
    const float* b3 = (const float*)d_in[6];
    float* out = (float*)d_out;

    const size_t smA = 38912u * 4u;   // 152 KB
    const size_t smB = 52288u * 4u;   // 204 KB
    cudaFuncSetAttribute(kA, cudaFuncAttributeMaxDynamicSharedMemorySize, (int)smA);
    cudaFuncSetAttribute(kB, cudaFuncAttributeMaxDynamicSharedMemorySize, (int)smB);

    kA<<<NBLK, 256, smA>>>(x, W1, b1, W2, b2);
    kB<<<NBLK, 256, smB>>>(x, W3, b3, out);
}